// round 1
// baseline (speedup 1.0000x reference)
#include <cuda_runtime.h>
#include <cuda_bf16.h>
#include <math.h>

#ifndef C_DIM
#define C_DIM 40
#endif

__global__ void init_out_kernel(float* out) {
    out[0] = 0.0f;
}

__global__ __launch_bounds__(256) void hier_loss_kernel(
    const float* __restrict__ logits,   // [B, 40]
    const int*   __restrict__ labels,   // [B]
    const float* __restrict__ dis,      // [40, 40]
    float* __restrict__ out,            // out[0]=loss, out[1..B]=distance_factor
    int B)
{
    int row = blockIdx.x * blockDim.x + threadIdx.x;

    float contrib = 0.0f;

    if (row < B) {
        const float4* rp = reinterpret_cast<const float4*>(logits + (long long)row * C_DIM);

        float v[C_DIM];
        #pragma unroll
        for (int i = 0; i < C_DIM / 4; i++) {
            float4 q = __ldg(rp + i);
            v[4 * i + 0] = q.x;
            v[4 * i + 1] = q.y;
            v[4 * i + 2] = q.z;
            v[4 * i + 3] = q.w;
        }

        // max + argmax (first occurrence wins, matching jnp.argmax)
        float mx = v[0];
        int   am = 0;
        #pragma unroll
        for (int i = 1; i < C_DIM; i++) {
            if (v[i] > mx) { mx = v[i]; am = i; }
        }

        // sum of exp(x - max)
        float s = 0.0f;
        #pragma unroll
        for (int i = 0; i < C_DIM; i++) {
            s += __expf(v[i] - mx);
        }

        int lbl = labels[row];
        // ce = logsumexp - x[label] = log(s) + mx - x[label]
        float ce = __logf(s) + mx - v[lbl];

        float df = __ldg(dis + lbl * C_DIM + am) + 0.5f;
        out[1 + row] = df;

        contrib = ce * df;
    }

    // block reduction of contrib
    __shared__ float sdata[256];
    int tid = threadIdx.x;
    sdata[tid] = contrib;
    __syncthreads();
    #pragma unroll
    for (int off = 128; off > 0; off >>= 1) {
        if (tid < off) sdata[tid] += sdata[tid + off];
        __syncthreads();
    }
    if (tid == 0) {
        atomicAdd(out, sdata[0] * (1.0f / (float)B));
    }
}

extern "C" void kernel_launch(void* const* d_in, const int* in_sizes, int n_in,
                              void* d_out, int out_size) {
    const float* logits = (const float*)d_in[0];
    const int*   labels = (const int*)d_in[1];
    const float* dis    = (const float*)d_in[2];
    float* out = (float*)d_out;

    int B = in_sizes[1];

    init_out_kernel<<<1, 1>>>(out);

    int threads = 256;
    int blocks = (B + threads - 1) / threads;
    hier_loss_kernel<<<blocks, threads>>>(logits, labels, dis, out, B);
}